// round 10
// baseline (speedup 1.0000x reference)
#include <cuda_runtime.h>
#include <cuda_bf16.h>
#include <cstdint>

// Problem constants (fixed by the reference)
#define NT      131072
#define HID     2048
#define NRANKS  8
#define NEXP    16
#define NSEG    128            // NRANKS * NEXP
#define VEC     (HID / 4)      // 512 float4 per row

// -------------------------------------------------------------------------
// Single fused SCATTER kernel: one block per INPUT row, 128 threads x
// 4 float4 each. Load addresses (input row i = blockIdx.x) are known at
// cycle 0, so all 4 streaming loads + scales[i] issue immediately; the
// redundant per-block segment-table scan hides under the DRAM latency.
// Only the stores (fire-and-forget) wait on the computed dst.
//
// dst resolution (no binary search): after the scans, thread tid holds
// input segment tid's exclusive offset off1 and count v1 in registers;
// the unique thread with off1 <= i < off1+v1 computes
//   dst = out_off[outp] + (i - off1),  outp = e*NRANKS + r,  tid = r*NEXP+e
// and broadcasts it through shared memory.
//
// Outputs (inverted): out_tokens[dst] = tokens[i]; scales_out[dst] =
// scales[i]; idx[dst] = i; block 0 writes expert_token_num.
// -------------------------------------------------------------------------
__global__ __launch_bounds__(128, 12)
void moe_scatter_kernel(const float4* __restrict__ tokens,
                        const int*    __restrict__ counts,
                        const float*  __restrict__ scales,
                        float*        __restrict__ out,
                        long long out_elems) {
    __shared__ int sc[NSEG];
    __shared__ int s_off2[NSEG];     // output-order exclusive cumsum
    __shared__ int warp_sums[8];     // [0..3]: scan1, [4..7]: scan2
    __shared__ int s_dst;

    const int tid = threadIdx.x;     // 0..127 == segment id
    const int i   = blockIdx.x;      // input row

    // ---- issue data loads FIRST (addresses known, hide the prologue) ----
    const float4* __restrict__ in = tokens + (long long)i * VEC;
    float4 a = __ldcs(in + tid);
    float4 b = __ldcs(in + tid + 128);
    float4 c = __ldcs(in + tid + 256);
    float4 d = __ldcs(in + tid + 384);
    float scv = 0.0f;
    if (tid == 0) scv = __ldg(&scales[i]);

    // ---- redundant per-block segment tables (hidden under loads) ----
    sc[tid] = __ldg(&counts[tid]);
    __syncthreads();

    const int lane = tid & 31, w = tid >> 5;
    const int e2 = tid >> 3, r2 = tid & 7;          // output-order segment

    // scan 1: input-order counts
    const int v1 = sc[tid];
    int incl1 = v1;
    #pragma unroll
    for (int dd = 1; dd < 32; dd <<= 1) {
        int y = __shfl_up_sync(0xffffffffu, incl1, dd);
        if (lane >= dd) incl1 += y;
    }
    // scan 2: output-order (permuted) counts
    const int v2 = sc[r2 * NEXP + e2];
    int incl2 = v2;
    #pragma unroll
    for (int dd = 1; dd < 32; dd <<= 1) {
        int y = __shfl_up_sync(0xffffffffu, incl2, dd);
        if (lane >= dd) incl2 += y;
    }
    if (lane == 31) { warp_sums[w] = incl1; warp_sums[4 + w] = incl2; }
    __syncthreads();

    int base1 = 0, base2 = 0;
    #pragma unroll
    for (int k = 0; k < 3; k++)
        if (k < w) { base1 += warp_sums[k]; base2 += warp_sums[4 + k]; }
    const int off1 = base1 + incl1 - v1;            // input-order exclusive
    s_off2[tid]    = base2 + incl2 - v2;            // output-order exclusive
    __syncthreads();

    // unique matching thread resolves dst
    if (off1 <= i && i < off1 + v1) {
        const int r = tid >> 4, e = tid & 15;       // input seg tid = r*NEXP+e
        const int outp = e * NRANKS + r;            // output-order position
        s_dst = s_off2[outp] + (i - off1);
    }
    __syncthreads();

    const int dst = s_dst;
    float4* __restrict__ o =
        reinterpret_cast<float4*>(out) + (long long)dst * VEC;
    __stcs(o + tid,       a);
    __stcs(o + tid + 128, b);
    __stcs(o + tid + 256, c);
    __stcs(o + tid + 384, d);

    const long long NH = (long long)NT * HID;
    if (tid == 0) {
        out[NH + dst]      = scv;         // permuted scales
        out[NH + NT + dst] = (float)i;    // idx[dst] = src row; < 2^24, exact
    }

    // expert_token_num tail (block 0 only)
    if (i == 0 && tid < NEXP) {
        int s = 0;
        #pragma unroll
        for (int rr = 0; rr < NRANKS; rr++) s += sc[rr * NEXP + tid];
        long long pos = NH + 2LL * NT + tid;
        if (pos < out_elems) out[pos] = (float)s;
    }
}

extern "C" void kernel_launch(void* const* d_in, const int* in_sizes, int n_in,
                              void* d_out, int out_size) {
    const float* tokens = (const float*)d_in[0];
    const int*   counts = (const int*)d_in[1];   // [NRANKS, NEXP]
    const float* scales = (const float*)d_in[2];
    float* out = (float*)d_out;

    moe_scatter_kernel<<<NT, 128>>>((const float4*)tokens, counts, scales, out,
                                    (long long)out_size);
}

// round 12
// speedup vs baseline: 1.0061x; 1.0061x over previous
#include <cuda_runtime.h>
#include <cuda_bf16.h>
#include <cstdint>

// Problem constants (fixed by the reference)
#define NT      131072
#define HID     2048
#define NRANKS  8
#define NEXP    16
#define NSEG    128            // NRANKS * NEXP
#define VEC     (HID / 4)      // 512 float4 per row

// -------------------------------------------------------------------------
// Single fused SCATTER kernel: one block per INPUT row, 256 threads x
// 2 float4 each (best-measured shape: 8 blocks/SM, 2048 thr/SM, 93% occ).
//
// The block's load address (input row i = blockIdx.x) is known at cycle 0,
// so both streaming loads + scales[i] issue immediately; the redundant
// per-block segment-table scan (~800 cyc) hides entirely under the DRAM
// load latency (~600+ cyc). Only the stores (fire-and-forget) wait on the
// computed destination row.
//
// dst resolution (no binary search): after the scans, thread tid<128 holds
// input segment tid's exclusive offset off1 and count v1 in registers; the
// unique thread with off1 <= i < off1+v1 computes
//   dst = out_off[outp] + (i - off1),  outp = e*NRANKS + r,  tid = r*NEXP+e
// and broadcasts it through shared memory.
//
// Outputs (inverted): out_tokens[dst] = tokens[i]; scales_out[dst] =
// scales[i]; idx[dst] = i; block 0 writes expert_token_num.
// -------------------------------------------------------------------------
__global__ __launch_bounds__(256, 8)
void moe_scatter_kernel(const float4* __restrict__ tokens,
                        const int*    __restrict__ counts,
                        const float*  __restrict__ scales,
                        float*        __restrict__ out) {
    __shared__ int sc[NSEG];
    __shared__ int s_off2[NSEG];     // output-order exclusive cumsum
    __shared__ int warp_sums[8];     // [0..3]: scan1, [4..7]: scan2
    __shared__ int s_dst;

    const int tid = threadIdx.x;
    const int i   = blockIdx.x;      // input row

    // ---- issue data loads FIRST (addresses known, hide the prologue) ----
    const float4* __restrict__ in = tokens + (long long)i * VEC;
    float4 a = __ldcs(in + tid);
    float4 b = __ldcs(in + tid + 256);
    float scv = 0.0f;
    if (tid == 0) scv = __ldg(&scales[i]);

    // ---- redundant per-block segment tables (hidden under loads) ----
    if (tid < NSEG) sc[tid] = __ldg(&counts[tid]);
    __syncthreads();

    int off1 = 0, v1 = 0;
    if (tid < NSEG) {
        const int lane = tid & 31, w = tid >> 5;
        const int e2 = tid >> 3, r2 = tid & 7;      // output-order segment

        // scan 1: input-order counts
        v1 = sc[tid];
        int incl1 = v1;
        #pragma unroll
        for (int d = 1; d < 32; d <<= 1) {
            int y = __shfl_up_sync(0xffffffffu, incl1, d);
            if (lane >= d) incl1 += y;
        }
        // scan 2: output-order (permuted) counts
        int v2 = sc[r2 * NEXP + e2];
        int incl2 = v2;
        #pragma unroll
        for (int d = 1; d < 32; d <<= 1) {
            int y = __shfl_up_sync(0xffffffffu, incl2, d);
            if (lane >= d) incl2 += y;
        }
        if (lane == 31) { warp_sums[w] = incl1; warp_sums[4 + w] = incl2; }
        __syncthreads();

        int base1 = 0, base2 = 0;
        #pragma unroll
        for (int k = 0; k < 3; k++)
            if (k < w) { base1 += warp_sums[k]; base2 += warp_sums[4 + k]; }
        off1 = base1 + incl1 - v1;                  // input-order exclusive
        s_off2[tid] = base2 + incl2 - v2;           // output-order exclusive
    } else {
        __syncthreads();
    }
    __syncthreads();

    // unique matching thread resolves dst
    if (tid < NSEG && off1 <= i && i < off1 + v1) {
        const int r = tid >> 4, e = tid & 15;       // input seg tid = r*NEXP+e
        const int outp = e * NRANKS + r;            // output-order position
        s_dst = s_off2[outp] + (i - off1);
    }
    __syncthreads();

    const int dst = s_dst;
    float4* __restrict__ o =
        reinterpret_cast<float4*>(out) + (long long)dst * VEC;
    __stcs(o + tid,       a);
    __stcs(o + tid + 256, b);

    const long long NH = (long long)NT * HID;
    if (tid == 0)  out[NH + dst] = scv;            // permuted scales
    if (tid == 32) out[NH + NT + dst] = (float)i;  // idx[dst]; < 2^24, exact

    // expert_token_num tail (block 0 only)
    if (i == 0 && tid >= 64 && tid < 64 + NEXP) {
        const int e = tid - 64;
        int s = 0;
        #pragma unroll
        for (int rr = 0; rr < NRANKS; rr++) s += sc[rr * NEXP + e];
        out[NH + 2LL * NT + e] = (float)s;
    }
}

extern "C" void kernel_launch(void* const* d_in, const int* in_sizes, int n_in,
                              void* d_out, int out_size) {
    const float* tokens = (const float*)d_in[0];
    const int*   counts = (const int*)d_in[1];   // [NRANKS, NEXP]
    const float* scales = (const float*)d_in[2];
    float* out = (float*)d_out;

    moe_scatter_kernel<<<NT, 256>>>((const float4*)tokens, counts, scales, out);
}

// round 13
// speedup vs baseline: 1.0081x; 1.0020x over previous
#include <cuda_runtime.h>
#include <cuda_bf16.h>
#include <cstdint>

// Problem constants (fixed by the reference)
#define NT      131072
#define HID     2048
#define NRANKS  8
#define NEXP    16
#define NSEG    128            // NRANKS * NEXP
#define VEC     (HID / 4)      // 512 float4 per row

// -------------------------------------------------------------------------
// Single fused SCATTER kernel: one block per INPUT row, 256 threads x
// 2 float4 each (best-measured shape: 8 blocks/SM, ~93% occupancy).
//
// The block's load address (input row i = blockIdx.x) is known at cycle 0,
// so both streaming loads + scales[i] issue immediately; the redundant
// per-block segment-table scan (~800 cyc) hides entirely under the DRAM
// load latency. Only the stores (fire-and-forget) wait on the computed dst.
//
// dst resolution (no binary search): after the scans, thread tid<128 holds
// input segment tid's exclusive offset off1 and count v1 in registers; the
// unique thread with off1 <= i < off1+v1 computes
//   dst = out_off[outp] + (i - off1),  outp = e*NRANKS + r,  tid = r*NEXP+e
// and broadcasts it through shared memory.
//
// Outputs (inverted permutation): out_tokens[dst] = tokens[i];
// scales_out[dst] = scales[i]; idx[dst] = i; block 0 writes
// expert_token_num.
//
// Measured: kernel ~299us @ DRAM 88.6% (7.0 TB/s) — at the chip's mixed
// read/write streaming ceiling; traffic (2.15 GB) is irreducible.
// -------------------------------------------------------------------------
__global__ __launch_bounds__(256, 8)
void moe_scatter_kernel(const float4* __restrict__ tokens,
                        const int*    __restrict__ counts,
                        const float*  __restrict__ scales,
                        float*        __restrict__ out,
                        long long out_elems) {
    __shared__ int sc[NSEG];
    __shared__ int s_off2[NSEG];     // output-order exclusive cumsum
    __shared__ int warp_sums[8];     // [0..3]: scan1, [4..7]: scan2
    __shared__ int s_dst;

    const int tid = threadIdx.x;
    const int i   = blockIdx.x;      // input row

    // ---- issue data loads FIRST (addresses known, hide the prologue) ----
    const float4* __restrict__ in = tokens + (long long)i * VEC;
    float4 a = __ldcs(in + tid);
    float4 b = __ldcs(in + tid + 256);
    float scv = 0.0f;
    if (tid == 0) scv = __ldg(&scales[i]);

    // ---- redundant per-block segment tables (hidden under loads) ----
    if (tid < NSEG) sc[tid] = __ldg(&counts[tid]);
    __syncthreads();

    int off1 = 0, v1 = 0;
    if (tid < NSEG) {
        const int lane = tid & 31, w = tid >> 5;
        const int e2 = tid >> 3, r2 = tid & 7;      // output-order segment

        // scan 1: input-order counts
        v1 = sc[tid];
        int incl1 = v1;
        #pragma unroll
        for (int d = 1; d < 32; d <<= 1) {
            int y = __shfl_up_sync(0xffffffffu, incl1, d);
            if (lane >= d) incl1 += y;
        }
        // scan 2: output-order (permuted) counts
        int v2 = sc[r2 * NEXP + e2];
        int incl2 = v2;
        #pragma unroll
        for (int d = 1; d < 32; d <<= 1) {
            int y = __shfl_up_sync(0xffffffffu, incl2, d);
            if (lane >= d) incl2 += y;
        }
        if (lane == 31) { warp_sums[w] = incl1; warp_sums[4 + w] = incl2; }
        __syncthreads();

        int base1 = 0, base2 = 0;
        #pragma unroll
        for (int k = 0; k < 3; k++)
            if (k < w) { base1 += warp_sums[k]; base2 += warp_sums[4 + k]; }
        off1 = base1 + incl1 - v1;                  // input-order exclusive
        s_off2[tid] = base2 + incl2 - v2;           // output-order exclusive
    } else {
        __syncthreads();
    }
    __syncthreads();

    // unique matching thread resolves dst
    if (tid < NSEG && off1 <= i && i < off1 + v1) {
        const int r = tid >> 4, e = tid & 15;       // input seg tid = r*NEXP+e
        const int outp = e * NRANKS + r;            // output-order position
        s_dst = s_off2[outp] + (i - off1);
    }
    __syncthreads();

    const int dst = s_dst;
    float4* __restrict__ o =
        reinterpret_cast<float4*>(out) + (long long)dst * VEC;
    __stcs(o + tid,       a);
    __stcs(o + tid + 256, b);

    const long long NH = (long long)NT * HID;
    if (tid == 0) {
        out[NH + dst]      = scv;         // permuted scales
        out[NH + NT + dst] = (float)i;    // idx[dst] = src row; < 2^24, exact
    }

    // expert_token_num tail (block 0 only)
    if (i == 0 && tid < NEXP) {
        int s = 0;
        #pragma unroll
        for (int rr = 0; rr < NRANKS; rr++) s += sc[rr * NEXP + tid];
        long long pos = NH + 2LL * NT + tid;
        if (pos < out_elems) out[pos] = (float)s;
    }
}

extern "C" void kernel_launch(void* const* d_in, const int* in_sizes, int n_in,
                              void* d_out, int out_size) {
    const float* tokens = (const float*)d_in[0];
    const int*   counts = (const int*)d_in[1];   // [NRANKS, NEXP]
    const float* scales = (const float*)d_in[2];
    float* out = (float*)d_out;

    moe_scatter_kernel<<<NT, 256>>>((const float4*)tokens, counts, scales, out,
                                    (long long)out_size);
}